// round 9
// baseline (speedup 1.0000x reference)
#include <cuda_runtime.h>
#include <cstdint>

// Problem constants (fixed shapes per reference)
#define BATCH 4
#define NNODES 4096          // N
#define CH 96                // C
#define N1 (NNODES + 1)      // 4097
#define PS 4                 // pooling_patch_size
#define NPATCH (NNODES / PS) // 1024
// tk = ps / reduction_ratio = 1

// Scratch: v[b][m] = sum_c sigmoid(nodes[b,m,c]) * theta[c]
__device__ float g_v[BATCH * NNODES];

__device__ __forceinline__ float fsig(float x) {
    // fast sigmoid: ~1e-7 rel err (EX2 + RCP on MUFU)
    return __fdividef(1.0f, 1.0f + __expf(-x));
}

// Kernel 1: v[b,m] = dot(sigmoid(x[b,1+m,:]), theta).
// 512 blocks x 256 threads, one warp handles 4 rows. Block 0 copies CLS rows.
__global__ __launch_bounds__(256) void node_score_kernel(
    const float* __restrict__ x, const float* __restrict__ theta,
    float* __restrict__ out)
{
    const int tid  = threadIdx.x;
    const int lane = tid & 31;
    const int gw   = blockIdx.x * 8 + (tid >> 5);   // global warp id, 0..4095

    const float t0 = theta[lane];
    const float t1 = theta[lane + 32];
    const float t2 = theta[lane + 64];

    if (blockIdx.x == 0) {
        for (int i = tid; i < BATCH * CH; i += 256) {
            const int bb = i / CH, c = i % CH;
            out[(size_t)bb * (NPATCH + 1) * CH + c] = x[(size_t)bb * N1 * CH + c];
        }
    }

#pragma unroll
    for (int r = 0; r < 4; r++) {
        const int row = gw + r * 4096;              // 0..16383
        const int b = row >> 12;
        const int m = row & (NNODES - 1);
        const float* xr = x + ((size_t)b * N1 + 1 + m) * CH;
        float s = fsig(xr[lane])      * t0
                + fsig(xr[lane + 32]) * t1
                + fsig(xr[lane + 64]) * t2;
#pragma unroll
        for (int off = 16; off > 0; off >>= 1)
            s += __shfl_down_sync(0xffffffffu, s, off);
        if (lane == 0) g_v[row] = s;
    }
}

// Kernel 2: per patch (b,p): scores for 4 rows = sum_m sigmoid(edge[b,row,m])*v[b,m],
// pick top-1 (first-index tie-break, matching jax top_k). NOTE: the reference
// gathers nodes[b, idx] where idx is the WITHIN-PATCH offset (0..3), not the
// absolute node index — reproduce that exactly.
//
// Access pattern: the 4 rows of a patch are CONTIGUOUS (64 KB dense block).
// Walk it linearly — slab k (k=0..15) is float4s [256k, 256k+256); row = k>>2,
// v-weight index = tid + 256*(k&3). One contiguous stream per block instead of
// four 16 KB-apart streams -> better DRAM page locality.
__global__ __launch_bounds__(256) void score_pool_kernel(
    const float* __restrict__ edge, const float* __restrict__ x,
    float* __restrict__ out)
{
    __shared__ float red[8][4];
    __shared__ float s_scale;
    __shared__ int   s_bidx;

    const int pg = blockIdx.x;         // 0..4095
    const int b  = pg >> 10;
    const int p  = pg & (NPATCH - 1);
    const int tid  = threadIdx.x;
    const int lane = tid & 31;
    const int wid  = tid >> 5;

    const float4* vv4 = (const float4*)(g_v + (b << 12));
    const float4* e0  = (const float4*)(edge + ((size_t)(b << 12) + (p << 2)) * NNODES);

    // Hoist the 4 v-weight vectors this thread ever needs (reused per row).
    float4 w[4];
#pragma unroll
    for (int j = 0; j < 4; j++) w[j] = vv4[tid + 256 * j];

    float acc[4] = {0.f, 0.f, 0.f, 0.f};
#pragma unroll
    for (int k = 0; k < 16; k++) {
        const float4 a = e0[tid + 256 * k];
        const float4 ww = w[k & 3];
        acc[k >> 2] += fsig(a.x)*ww.x + fsig(a.y)*ww.y
                     + fsig(a.z)*ww.z + fsig(a.w)*ww.w;
    }

    float s0 = acc[0], s1 = acc[1], s2 = acc[2], s3 = acc[3];
#pragma unroll
    for (int off = 16; off > 0; off >>= 1) {
        s0 += __shfl_down_sync(0xffffffffu, s0, off);
        s1 += __shfl_down_sync(0xffffffffu, s1, off);
        s2 += __shfl_down_sync(0xffffffffu, s2, off);
        s3 += __shfl_down_sync(0xffffffffu, s3, off);
    }
    if (lane == 0) {
        red[wid][0] = s0; red[wid][1] = s1; red[wid][2] = s2; red[wid][3] = s3;
    }
    __syncthreads();

    if (tid == 0) {
        float sc[4];
#pragma unroll
        for (int r = 0; r < 4; r++) {
            float t = 0.f;
#pragma unroll
            for (int w2 = 0; w2 < 8; w2++) t += red[w2][r];
            sc[r] = t;
        }
        // top-1 with lowest-index tie-break (strict >)
        float best = sc[0]; int bi = 0;
#pragma unroll
        for (int r = 1; r < 4; r++)
            if (sc[r] > best) { best = sc[r]; bi = r; }
        s_scale = best + 1.0f;   // pooled = vals*g + g = (vals+1)*g
        s_bidx  = bi;
    }
    __syncthreads();

    if (tid < CH) {
        const int gidx = s_bidx;   // reference uses the raw within-patch index!
        const float g  = x[((size_t)b * N1 + 1 + gidx) * CH + tid];
        out[((size_t)b * (NPATCH + 1) + 1 + p) * CH + tid] = s_scale * g;
    }
}

extern "C" void kernel_launch(void* const* d_in, const int* in_sizes, int n_in,
                              void* d_out, int out_size)
{
    const float* x     = (const float*)d_in[0];  // (4,4097,96) f32
    const float* edge  = (const float*)d_in[1];  // (4,4096,4096) f32
    const float* theta = (const float*)d_in[2];  // (1,96) f32
    float* out = (float*)d_out;                  // (4,1025,96) f32

    node_score_kernel<<<512, 256>>>(x, theta, out);
    score_pool_kernel<<<BATCH * NPATCH, 256>>>(edge, x, out);
}

// round 10
// speedup vs baseline: 1.0103x; 1.0103x over previous
#include <cuda_runtime.h>
#include <cstdint>

// Problem constants (fixed shapes per reference)
#define BATCH 4
#define NNODES 4096          // N
#define CH 96                // C
#define N1 (NNODES + 1)      // 4097
#define PS 4                 // pooling_patch_size
#define NPATCH (NNODES / PS) // 1024
// tk = ps / reduction_ratio = 1

// Scratch: v[b][m] = sum_c sigmoid(nodes[b,m,c]) * theta[c]
__device__ float g_v[BATCH * NNODES];

__device__ __forceinline__ float fsig(float x) {
    // fast sigmoid: ~1e-7 rel err (EX2 + RCP on MUFU)
    return __fdividef(1.0f, 1.0f + __expf(-x));
}

// Kernel 1: v[b,m] = dot(sigmoid(x[b,1+m,:]), theta).
// 2048 blocks x 256 threads -> 16384 warps, exactly one row per warp
// (no loop-carried chain). theta in registers. Block 0 copies CLS rows.
__global__ __launch_bounds__(256) void node_score_kernel(
    const float* __restrict__ x, const float* __restrict__ theta,
    float* __restrict__ out)
{
    const int tid  = threadIdx.x;
    const int lane = tid & 31;
    const int row  = blockIdx.x * 8 + (tid >> 5);   // 0..16383

    const float t0 = theta[lane];
    const float t1 = theta[lane + 32];
    const float t2 = theta[lane + 64];

    if (blockIdx.x == 0) {
        // CLS rows: 4*96 = 384 elements
        for (int i = tid; i < BATCH * CH; i += 256) {
            const int bb = i / CH, c = i % CH;
            out[(size_t)bb * (NPATCH + 1) * CH + c] = x[(size_t)bb * N1 * CH + c];
        }
    }

    const int b = row >> 12;
    const int m = row & (NNODES - 1);
    const float* xr = x + ((size_t)b * N1 + 1 + m) * CH;
    float s = fsig(xr[lane])      * t0
            + fsig(xr[lane + 32]) * t1
            + fsig(xr[lane + 64]) * t2;
#pragma unroll
    for (int off = 16; off > 0; off >>= 1)
        s += __shfl_down_sync(0xffffffffu, s, off);
    if (lane == 0) g_v[row] = s;
}

// Kernel 2 (R2/R8 body — empirically at the chip's effective HBM ceiling,
// ~6.08 TB/s; five controlled variants all regressed. DO NOT TOUCH.):
// per patch (b,p): scores for 4 rows = sum_m sigmoid(edge[b,row,m])*v[b,m],
// pick top-1 (first-index tie-break, matching jax top_k). NOTE: the reference
// gathers nodes[b, idx] where idx is the WITHIN-PATCH offset (0..3), not the
// absolute node index — reproduce that exactly.
__global__ __launch_bounds__(256) void score_pool_kernel(
    const float* __restrict__ edge, const float* __restrict__ x,
    float* __restrict__ out)
{
    __shared__ float red[8][4];
    __shared__ float s_scale;
    __shared__ int   s_bidx;

    const int pg = blockIdx.x;         // 0..4095
    const int b  = pg >> 10;
    const int p  = pg & (NPATCH - 1);
    const int tid  = threadIdx.x;
    const int lane = tid & 31;
    const int wid  = tid >> 5;

    const float4* vv4 = (const float4*)(g_v + (b << 12));
    const float4* e0  = (const float4*)(edge + ((size_t)(b << 12) + (p << 2)) * NNODES);
    // row stride in float4 units: 4096/4 = 1024

    float s0 = 0.f, s1 = 0.f, s2 = 0.f, s3 = 0.f;
#pragma unroll
    for (int i = tid; i < 1024; i += 256) {
        const float4 w  = vv4[i];
        const float4 a0 = e0[i];
        const float4 a1 = e0[i + 1024];
        const float4 a2 = e0[i + 2048];
        const float4 a3 = e0[i + 3072];
        s0 += fsig(a0.x)*w.x + fsig(a0.y)*w.y + fsig(a0.z)*w.z + fsig(a0.w)*w.w;
        s1 += fsig(a1.x)*w.x + fsig(a1.y)*w.y + fsig(a1.z)*w.z + fsig(a1.w)*w.w;
        s2 += fsig(a2.x)*w.x + fsig(a2.y)*w.y + fsig(a2.z)*w.z + fsig(a2.w)*w.w;
        s3 += fsig(a3.x)*w.x + fsig(a3.y)*w.y + fsig(a3.z)*w.z + fsig(a3.w)*w.w;
    }

#pragma unroll
    for (int off = 16; off > 0; off >>= 1) {
        s0 += __shfl_down_sync(0xffffffffu, s0, off);
        s1 += __shfl_down_sync(0xffffffffu, s1, off);
        s2 += __shfl_down_sync(0xffffffffu, s2, off);
        s3 += __shfl_down_sync(0xffffffffu, s3, off);
    }
    if (lane == 0) {
        red[wid][0] = s0; red[wid][1] = s1; red[wid][2] = s2; red[wid][3] = s3;
    }
    __syncthreads();

    if (tid == 0) {
        float sc[4];
#pragma unroll
        for (int r = 0; r < 4; r++) {
            float t = 0.f;
#pragma unroll
            for (int w = 0; w < 8; w++) t += red[w][r];
            sc[r] = t;
        }
        // top-1 with lowest-index tie-break (strict >)
        float best = sc[0]; int bi = 0;
#pragma unroll
        for (int r = 1; r < 4; r++)
            if (sc[r] > best) { best = sc[r]; bi = r; }
        s_scale = best + 1.0f;   // pooled = vals*g + g = (vals+1)*g
        s_bidx  = bi;
    }
    __syncthreads();

    if (tid < CH) {
        const int gidx = s_bidx;   // reference uses the raw within-patch index!
        const float g  = x[((size_t)b * N1 + 1 + gidx) * CH + tid];
        out[((size_t)b * (NPATCH + 1) + 1 + p) * CH + tid] = s_scale * g;
    }
}

extern "C" void kernel_launch(void* const* d_in, const int* in_sizes, int n_in,
                              void* d_out, int out_size)
{
    const float* x     = (const float*)d_in[0];  // (4,4097,96) f32
    const float* edge  = (const float*)d_in[1];  // (4,4096,4096) f32
    const float* theta = (const float*)d_in[2];  // (1,96) f32
    float* out = (float*)d_out;                  // (4,1025,96) f32

    node_score_kernel<<<2048, 256>>>(x, theta, out);
    score_pool_kernel<<<BATCH * NPATCH, 256>>>(edge, x, out);
}